// round 12
// baseline (speedup 1.0000x reference)
#include <cuda_runtime.h>

#define NN 100000
#define EE 1600000
#define BLK 256
#define EGRID 1184   // 148 SMs * 8 blocks => exactly one full-occupancy wave

// ---- device scratch (zero-initialized at load; kernels restore the zero
//      invariants they consume, so graph replays stay deterministic) ----
__device__ int    g_src32[EE];
__device__ int    g_dst32[EE];
__device__ float  g_deg[NN];       // zeroed by k_node1 after use
__device__ float  g_dinv[NN];
__device__ float  g_px[NN];
__device__ float  g_s[NN];
__device__ float2 g_pq[NN];
__device__ float2 g_PQ[NN];
__device__ float  g_agg[NN * 16];  // fallback; zeroed by k_out after use
__device__ float  g_c[64];
__device__ int    g_b1zero;
__device__ int    g_is64;

__device__ __forceinline__ int4 ldcs4(const int* p) {
    return __ldcs(reinterpret_cast<const int4*>(p));
}

__device__ __forceinline__ void red2(float2* addr, float2 v) {
    asm volatile("red.add.v2.f32 [%0], {%1, %2};"
                 :: "l"(addr), "f"(v.x), "f"(v.y) : "memory");
}

// ---- setup: dtype probe + fused coefficients (single block) ----
__global__ void k_setup(const void* __restrict__ ei, const float* __restrict__ W1,
                        const float* __restrict__ b1, const float* __restrict__ W2,
                        int E, int N) {
    int tid = threadIdx.x;
    __shared__ int bad;
    if (tid == 0) bad = 0;
    __syncthreads();
    if (tid < E) {
        long long v = ((const long long*)ei)[tid];  // first 256 slots in-bounds both layouts
        if (v < 0 || v >= (long long)N) atomicExch(&bad, 1);
    }
    __syncthreads();
    if (tid == 0) {
        g_is64 = !bad;
        int z = 1;
        for (int k = 0; k < 16; k++)
            if (b1[k] != 0.f) z = 0;
        g_b1zero = z;
    }
    if (tid < 32) {
        float c1 = 0.f, c2 = 0.f;
#pragma unroll
        for (int k = 0; k < 16; k++) {
            float w  = W1[k];
            float wv = W2[k * 32 + tid];
            c1 += fmaxf(w, 0.f) * wv;
            c2 += fminf(w, 0.f) * wv;
        }
        g_c[tid] = c1;
        g_c[32 + tid] = c2;
    }
}

// ---- pass 1: degree REDs (+ one-time int64->int32 conversion), single-wave ----
__global__ void __launch_bounds__(BLK) k_deg(const void* __restrict__ eiv, int E) {
    int t = blockIdx.x * BLK + threadIdx.x;
    int T = EGRID * BLK;
    int e4 = 4 * t;
    if (g_is64) {
        const long long* ei = (const long long*)eiv;
        if (e4 + 3 < E && e4 + 3 < 4 * T) {
            longlong2 sA = __ldcs(reinterpret_cast<const longlong2*>(ei + e4));
            longlong2 sB = __ldcs(reinterpret_cast<const longlong2*>(ei + e4 + 2));
            longlong2 dA = __ldcs(reinterpret_cast<const longlong2*>(ei + E + e4));
            longlong2 dB = __ldcs(reinterpret_cast<const longlong2*>(ei + E + e4 + 2));
            int4 sv = make_int4((int)sA.x, (int)sA.y, (int)sB.x, (int)sB.y);
            int4 dv = make_int4((int)dA.x, (int)dA.y, (int)dB.x, (int)dB.y);
            *reinterpret_cast<int4*>(&g_src32[e4]) = sv;
            *reinterpret_cast<int4*>(&g_dst32[e4]) = dv;
            atomicAdd(&g_deg[dv.x], 1.f); atomicAdd(&g_deg[dv.y], 1.f);
            atomicAdd(&g_deg[dv.z], 1.f); atomicAdd(&g_deg[dv.w], 1.f);
        }
        // scalar tail segment [4T, E) grid-stride (also covers the int4-segment ragged edge)
        int tail0 = min(4 * T, E & ~3);
        for (int e = e4; e < E && e < tail0; e++) { /* covered above when full quad */ }
        for (int e = tail0 + t; e < E; e += T) {
            int s = (int)ei[e], d = (int)ei[E + e];
            g_src32[e] = s; g_dst32[e] = d;
            atomicAdd(&g_deg[d], 1.f);
        }
        // ragged quad (when E not multiple of 4 inside int4 segment)
        if (e4 < E && e4 + 3 >= E && e4 < 4 * T) {
            for (int e = e4; e < E; e++) {
                int s = (int)ei[e], d = (int)ei[E + e];
                g_src32[e] = s; g_dst32[e] = d;
                atomicAdd(&g_deg[d], 1.f);
            }
        }
    } else {
        const int* dst = (const int*)eiv + E;
        if (e4 + 3 < E && e4 + 3 < 4 * T) {
            int4 dv = ldcs4(dst + e4);
            atomicAdd(&g_deg[dv.x], 1.f); atomicAdd(&g_deg[dv.y], 1.f);
            atomicAdd(&g_deg[dv.z], 1.f); atomicAdd(&g_deg[dv.w], 1.f);
        }
        int tail0 = min(4 * T, E & ~3);
        for (int e = tail0 + t; e < E; e += T)
            atomicAdd(&g_deg[dst[e]], 1.f);
        if (e4 < E && e4 + 3 >= E && e4 < 4 * T) {
            for (int e = e4; e < E; e++) atomicAdd(&g_deg[dst[e]], 1.f);
        }
    }
}

// ---- pass 2: dinv; px; raw s init; restore g_deg zero invariant ----
__global__ void k_node1(const float* __restrict__ x, int n) {
    int v = blockIdx.x * blockDim.x + threadIdx.x;
    if (v >= n) return;
    float dg = g_deg[v];
    g_deg[v] = 0.f;                    // reset for next graph replay
    float dv  = rsqrtf(dg + 1.0f);
    g_dinv[v] = dv;
    float pxv = dv * x[v];
    g_px[v]   = pxv;
    g_s[v]    = pxv;                   // self-loop contribution to raw sum
}

// ---- pass 3: layer-1 raw scatter, single-wave, int4 quad + scalar tail ----
__global__ void __launch_bounds__(BLK) k_scat1(const void* __restrict__ eiv, int E) {
    const int* srcp = g_is64 ? g_src32 : (const int*)eiv;
    const int* dstp = g_is64 ? g_dst32 : (const int*)eiv + E;
    int t = blockIdx.x * BLK + threadIdx.x;
    int T = EGRID * BLK;
    int e4 = 4 * t;
    if (e4 + 3 < E && e4 + 3 < 4 * T) {
        int4 s = ldcs4(srcp + e4);
        int4 d = ldcs4(dstp + e4);
        float a0 = __ldg(&g_px[s.x]), a1 = __ldg(&g_px[s.y]);
        float a2 = __ldg(&g_px[s.z]), a3 = __ldg(&g_px[s.w]);
        atomicAdd(&g_s[d.x], a0); atomicAdd(&g_s[d.y], a1);
        atomicAdd(&g_s[d.z], a2); atomicAdd(&g_s[d.w], a3);
    }
    int tail0 = min(4 * T, E & ~3);
    for (int e = tail0 + t; e < E; e += T)
        atomicAdd(&g_s[dstp[e]], __ldg(&g_px[srcp[e]]));
    if (e4 < E && e4 + 3 >= E && e4 < 4 * T) {
        for (int e = e4; e < E; e++)
            atomicAdd(&g_s[dstp[e]], __ldg(&g_px[srcp[e]]));
    }
}

// ---- pass 4: finalize s; pq split; PQ init = self term ----
__global__ void k_node2(int n) {
    int v = blockIdx.x * blockDim.x + threadIdx.x;
    if (v >= n) return;
    float dv = g_dinv[v];
    float s  = dv * g_s[v];
    g_s[v]   = s;
    float p = fmaxf(s, 0.f), q = fminf(s, 0.f);
    float2 pq = make_float2(dv * p, dv * q);
    g_pq[v] = pq;
    g_PQ[v] = pq;
}

// ---- pass 5: layer-2 raw scatter, single-wave, 1 v2-RED/edge ----
__global__ void __launch_bounds__(BLK) k_scat2(const void* __restrict__ eiv,
                                               const float* __restrict__ W1,
                                               const float* __restrict__ b1, int E) {
    const int* srcp = g_is64 ? g_src32 : (const int*)eiv;
    const int* dstp = g_is64 ? g_dst32 : (const int*)eiv + E;
    int bz = g_b1zero;
    int t = blockIdx.x * BLK + threadIdx.x;
    int T = EGRID * BLK;
    int e4 = 4 * t;
    if (bz) {
        if (e4 + 3 < E && e4 + 3 < 4 * T) {
            int4 s = ldcs4(srcp + e4);
            int4 d = ldcs4(dstp + e4);
            float2 t0 = __ldg(&g_pq[s.x]), t1 = __ldg(&g_pq[s.y]);
            float2 t2 = __ldg(&g_pq[s.z]), t3 = __ldg(&g_pq[s.w]);
            red2(&g_PQ[d.x], t0); red2(&g_PQ[d.y], t1);
            red2(&g_PQ[d.z], t2); red2(&g_PQ[d.w], t3);
        }
        int tail0 = min(4 * T, E & ~3);
        for (int e = tail0 + t; e < E; e += T)
            red2(&g_PQ[dstp[e]], __ldg(&g_pq[srcp[e]]));
        if (e4 < E && e4 + 3 >= E && e4 < 4 * T) {
            for (int e = e4; e < E; e++)
                red2(&g_PQ[dstp[e]], __ldg(&g_pq[srcp[e]]));
        }
    } else {
        __shared__ float sW1[16], sb1[16];
        if (threadIdx.x < 16) { sW1[threadIdx.x] = W1[threadIdx.x]; sb1[threadIdx.x] = b1[threadIdx.x]; }
        __syncthreads();
        for (int e = 4 * t; e < min(4 * t + 4, min(4 * T, E)); e++) {
            int s = srcp[e], d = dstp[e];
            float sv = __ldg(&g_s[s]);
            float ns = __ldg(&g_dinv[s]);
#pragma unroll
            for (int k = 0; k < 16; k++) {
                float h = fmaxf(sv * sW1[k] + sb1[k], 0.f);
                atomicAdd(&g_agg[(size_t)d * 16 + k], ns * h);
            }
        }
        for (int e = 4 * T + t; e < E; e += T) {
            int s = srcp[e], d = dstp[e];
            float sv = __ldg(&g_s[s]);
            float ns = __ldg(&g_dinv[s]);
#pragma unroll
            for (int k = 0; k < 16; k++) {
                float h = fmaxf(sv * sW1[k] + sb1[k], 0.f);
                atomicAdd(&g_agg[(size_t)d * 16 + k], ns * h);
            }
        }
    }
}

// ---- pass 6: output projection (fallback path restores g_agg zero invariant) ----
__global__ void k_out(const float* __restrict__ W1, const float* __restrict__ b1,
                      const float* __restrict__ W2, const float* __restrict__ b2,
                      float* __restrict__ out, int n) {
    __shared__ float sc[64];
    __shared__ float sb2[32];
    __shared__ float sW2[512];
    __shared__ float sW1[16], sb1[16];
    int bz = g_b1zero;
    int t = threadIdx.x;
    if (t < 64) sc[t] = g_c[t];
    if (t < 32) sb2[t] = b2[t];
    if (!bz) {
        for (int k = t; k < 512; k += blockDim.x) sW2[k] = W2[k];
        if (t < 16) { sW1[t] = W1[t]; sb1[t] = b1[t]; }
    }
    __syncthreads();
    int v = blockIdx.x * blockDim.x + t;
    if (v >= n) return;

    float o[32];
    float dv = g_dinv[v];
    if (bz) {
        float2 PQ = g_PQ[v];
        float P = dv * PQ.x, Q = dv * PQ.y;
#pragma unroll
        for (int j = 0; j < 32; j++) o[j] = P * sc[j] + Q * sc[32 + j] + sb2[j];
    } else {
        float sv = g_s[v];
        float n2 = dv * dv;
        float tot[16];
        float4* a = reinterpret_cast<float4*>(&g_agg[(size_t)v * 16]);
        float4 z = make_float4(0.f, 0.f, 0.f, 0.f);
#pragma unroll
        for (int q4 = 0; q4 < 4; q4++) {
            float4 av = a[q4];
            a[q4] = z;                 // reset invariant for next replay
            tot[4 * q4 + 0] = av.x; tot[4 * q4 + 1] = av.y;
            tot[4 * q4 + 2] = av.z; tot[4 * q4 + 3] = av.w;
        }
#pragma unroll
        for (int k = 0; k < 16; k++) {
            float h = fmaxf(sv * sW1[k] + sb1[k], 0.f);
            tot[k] = dv * tot[k] + n2 * h;
        }
#pragma unroll
        for (int j = 0; j < 32; j++) {
            float acc = sb2[j];
#pragma unroll
            for (int k = 0; k < 16; k++) acc += tot[k] * sW2[k * 32 + j];
            o[j] = acc;
        }
    }
    float4* po = reinterpret_cast<float4*>(out + (size_t)v * 32);
#pragma unroll
    for (int j = 0; j < 8; j++)
        __stcs(po + j, make_float4(o[4 * j], o[4 * j + 1], o[4 * j + 2], o[4 * j + 3]));
}

extern "C" void kernel_launch(void* const* d_in, const int* in_sizes, int n_in,
                              void* d_out, int out_size) {
    const float* x  = (const float*)d_in[0];
    const void*  ei = d_in[1];
    const float* W1 = (const float*)d_in[2];
    const float* b1 = (const float*)d_in[3];
    const float* W2 = (const float*)d_in[4];
    const float* b2 = (const float*)d_in[5];
    float* out = (float*)d_out;

    int N = in_sizes[0];
    int E = in_sizes[1] / 2;

    int gN = (N + BLK - 1) / BLK;

    k_setup<<<1, BLK>>>(ei, W1, b1, W2, E, N);
    k_deg<<<EGRID, BLK>>>(ei, E);
    k_node1<<<gN, BLK>>>(x, N);
    k_scat1<<<EGRID, BLK>>>(ei, E);
    k_node2<<<gN, BLK>>>(N);
    k_scat2<<<EGRID, BLK>>>(ei, W1, b1, E);
    k_out<<<gN, BLK>>>(W1, b1, W2, b2, out, N);
}

// round 13
// speedup vs baseline: 1.0290x; 1.0290x over previous
#include <cuda_runtime.h>

#define NN 100000
#define EE 1600000
#define BLK 256
#define EGRID 1184   // 148 SMs * 8 blocks => one full-occupancy wave

// ---- device scratch (zero-initialized at load; kernels restore the zero
//      invariants they consume, so graph replays stay deterministic) ----
__device__ int    g_src32[EE];
__device__ int    g_dst32[EE];
__device__ float  g_deg[NN];       // zeroed by k_node1 after use
__device__ float  g_dinv[NN];
__device__ float  g_px[NN];
__device__ float  g_s[NN];
__device__ float2 g_pq[NN];
__device__ float2 g_PQ[NN];
__device__ float  g_agg[NN * 16];  // fallback; zeroed by k_out after use
__device__ float  g_c[64];
__device__ int    g_b1zero;
__device__ int    g_is64;

__device__ __forceinline__ int4 ld4(const int* p) {
    return *reinterpret_cast<const int4*>(p);   // L2-cacheable (edges are reused across passes)
}

__device__ __forceinline__ void red2(float2* addr, float2 v) {
    asm volatile("red.add.v2.f32 [%0], {%1, %2};"
                 :: "l"(addr), "f"(v.x), "f"(v.y) : "memory");
}

// ---- setup: dtype probe + fused coefficients (single block) ----
__global__ void k_setup(const void* __restrict__ ei, const float* __restrict__ W1,
                        const float* __restrict__ b1, const float* __restrict__ W2,
                        int E, int N) {
    int tid = threadIdx.x;
    __shared__ int bad;
    if (tid == 0) bad = 0;
    __syncthreads();
    if (tid < E) {
        long long v = ((const long long*)ei)[tid];  // first 256 slots in-bounds both layouts
        if (v < 0 || v >= (long long)N) atomicExch(&bad, 1);
    }
    __syncthreads();
    if (tid == 0) {
        g_is64 = !bad;
        int z = 1;
        for (int k = 0; k < 16; k++)
            if (b1[k] != 0.f) z = 0;
        g_b1zero = z;
    }
    if (tid < 32) {
        float c1 = 0.f, c2 = 0.f;
#pragma unroll
        for (int k = 0; k < 16; k++) {
            float w  = W1[k];
            float wv = W2[k * 32 + tid];
            c1 += fmaxf(w, 0.f) * wv;
            c2 += fminf(w, 0.f) * wv;
        }
        g_c[tid] = c1;
        g_c[32 + tid] = c2;
    }
}

// ---- pass 1: degree REDs (+ int64->int32 conversion); warms edges into L2 ----
__global__ void __launch_bounds__(BLK) k_deg(const void* __restrict__ eiv, int E) {
    int t = blockIdx.x * BLK + threadIdx.x;
    int T = EGRID * BLK;
    int e4 = 4 * t;
    if (g_is64) {
        const long long* ei = (const long long*)eiv;
        if (e4 + 3 < E && e4 + 3 < 4 * T) {
            longlong2 sA = *reinterpret_cast<const longlong2*>(ei + e4);
            longlong2 sB = *reinterpret_cast<const longlong2*>(ei + e4 + 2);
            longlong2 dA = *reinterpret_cast<const longlong2*>(ei + E + e4);
            longlong2 dB = *reinterpret_cast<const longlong2*>(ei + E + e4 + 2);
            int4 sv = make_int4((int)sA.x, (int)sA.y, (int)sB.x, (int)sB.y);
            int4 dv = make_int4((int)dA.x, (int)dA.y, (int)dB.x, (int)dB.y);
            *reinterpret_cast<int4*>(&g_src32[e4]) = sv;
            *reinterpret_cast<int4*>(&g_dst32[e4]) = dv;
            atomicAdd(&g_deg[dv.x], 1.f); atomicAdd(&g_deg[dv.y], 1.f);
            atomicAdd(&g_deg[dv.z], 1.f); atomicAdd(&g_deg[dv.w], 1.f);
        }
        int tail0 = min(4 * T, E & ~3);
        for (int e = tail0 + t; e < E; e += T) {
            int s = (int)ei[e], d = (int)ei[E + e];
            g_src32[e] = s; g_dst32[e] = d;
            atomicAdd(&g_deg[d], 1.f);
        }
        if (e4 < E && e4 + 3 >= E && e4 < 4 * T) {
            for (int e = e4; e < E; e++) {
                int s = (int)ei[e], d = (int)ei[E + e];
                g_src32[e] = s; g_dst32[e] = d;
                atomicAdd(&g_deg[d], 1.f);
            }
        }
    } else {
        const int* base = (const int*)eiv;
        const int* dst  = base + E;
        if (e4 + 3 < E && e4 + 3 < 4 * T) {
            int4 dv = ld4(dst + e4);
            int4 sv = ld4(base + e4);   // touch src half too: warm it into L2 for scat1
            (void)sv;
            atomicAdd(&g_deg[dv.x], 1.f); atomicAdd(&g_deg[dv.y], 1.f);
            atomicAdd(&g_deg[dv.z], 1.f); atomicAdd(&g_deg[dv.w], 1.f);
        }
        int tail0 = min(4 * T, E & ~3);
        for (int e = tail0 + t; e < E; e += T)
            atomicAdd(&g_deg[dst[e]], 1.f);
        if (e4 < E && e4 + 3 >= E && e4 < 4 * T) {
            for (int e = e4; e < E; e++) atomicAdd(&g_deg[dst[e]], 1.f);
        }
    }
}

// ---- pass 2: dinv; px; raw s init; restore g_deg zero invariant ----
__global__ void k_node1(const float* __restrict__ x, int n) {
    int v = blockIdx.x * blockDim.x + threadIdx.x;
    if (v >= n) return;
    float dg = g_deg[v];
    g_deg[v] = 0.f;                    // reset for next graph replay
    float dv  = rsqrtf(dg + 1.0f);
    g_dinv[v] = dv;
    float pxv = dv * x[v];
    g_px[v]   = pxv;
    g_s[v]    = pxv;                   // self-loop contribution to raw sum
}

// ---- pass 3: layer-1 raw scatter (edges now L2-hot) ----
__global__ void __launch_bounds__(BLK) k_scat1(const void* __restrict__ eiv, int E) {
    const int* srcp = g_is64 ? g_src32 : (const int*)eiv;
    const int* dstp = g_is64 ? g_dst32 : (const int*)eiv + E;
    int t = blockIdx.x * BLK + threadIdx.x;
    int T = EGRID * BLK;
    int e4 = 4 * t;
    if (e4 + 3 < E && e4 + 3 < 4 * T) {
        int4 s = ld4(srcp + e4);
        int4 d = ld4(dstp + e4);
        float a0 = __ldg(&g_px[s.x]), a1 = __ldg(&g_px[s.y]);
        float a2 = __ldg(&g_px[s.z]), a3 = __ldg(&g_px[s.w]);
        atomicAdd(&g_s[d.x], a0); atomicAdd(&g_s[d.y], a1);
        atomicAdd(&g_s[d.z], a2); atomicAdd(&g_s[d.w], a3);
    }
    int tail0 = min(4 * T, E & ~3);
    for (int e = tail0 + t; e < E; e += T)
        atomicAdd(&g_s[dstp[e]], __ldg(&g_px[srcp[e]]));
    if (e4 < E && e4 + 3 >= E && e4 < 4 * T) {
        for (int e = e4; e < E; e++)
            atomicAdd(&g_s[dstp[e]], __ldg(&g_px[srcp[e]]));
    }
}

// ---- pass 4: finalize s; pq split; PQ init = self term ----
__global__ void k_node2(int n) {
    int v = blockIdx.x * blockDim.x + threadIdx.x;
    if (v >= n) return;
    float dv = g_dinv[v];
    float s  = dv * g_s[v];
    g_s[v]   = s;
    float p = fmaxf(s, 0.f), q = fminf(s, 0.f);
    float2 pq = make_float2(dv * p, dv * q);
    g_pq[v] = pq;
    g_PQ[v] = pq;
}

// ---- pass 5: layer-2 raw scatter (edges L2-hot), 1 v2-RED/edge ----
__global__ void __launch_bounds__(BLK) k_scat2(const void* __restrict__ eiv,
                                               const float* __restrict__ W1,
                                               const float* __restrict__ b1, int E) {
    const int* srcp = g_is64 ? g_src32 : (const int*)eiv;
    const int* dstp = g_is64 ? g_dst32 : (const int*)eiv + E;
    int bz = g_b1zero;
    int t = blockIdx.x * BLK + threadIdx.x;
    int T = EGRID * BLK;
    int e4 = 4 * t;
    if (bz) {
        if (e4 + 3 < E && e4 + 3 < 4 * T) {
            int4 s = ld4(srcp + e4);
            int4 d = ld4(dstp + e4);
            float2 t0 = __ldg(&g_pq[s.x]), t1 = __ldg(&g_pq[s.y]);
            float2 t2 = __ldg(&g_pq[s.z]), t3 = __ldg(&g_pq[s.w]);
            red2(&g_PQ[d.x], t0); red2(&g_PQ[d.y], t1);
            red2(&g_PQ[d.z], t2); red2(&g_PQ[d.w], t3);
        }
        int tail0 = min(4 * T, E & ~3);
        for (int e = tail0 + t; e < E; e += T)
            red2(&g_PQ[dstp[e]], __ldg(&g_pq[srcp[e]]));
        if (e4 < E && e4 + 3 >= E && e4 < 4 * T) {
            for (int e = e4; e < E; e++)
                red2(&g_PQ[dstp[e]], __ldg(&g_pq[srcp[e]]));
        }
    } else {
        __shared__ float sW1[16], sb1[16];
        if (threadIdx.x < 16) { sW1[threadIdx.x] = W1[threadIdx.x]; sb1[threadIdx.x] = b1[threadIdx.x]; }
        __syncthreads();
        for (int e = 4 * t; e < min(4 * t + 4, min(4 * T, E)); e++) {
            int s = srcp[e], d = dstp[e];
            float sv = __ldg(&g_s[s]);
            float ns = __ldg(&g_dinv[s]);
#pragma unroll
            for (int k = 0; k < 16; k++) {
                float h = fmaxf(sv * sW1[k] + sb1[k], 0.f);
                atomicAdd(&g_agg[(size_t)d * 16 + k], ns * h);
            }
        }
        for (int e = 4 * T + t; e < E; e += T) {
            int s = srcp[e], d = dstp[e];
            float sv = __ldg(&g_s[s]);
            float ns = __ldg(&g_dinv[s]);
#pragma unroll
            for (int k = 0; k < 16; k++) {
                float h = fmaxf(sv * sW1[k] + sb1[k], 0.f);
                atomicAdd(&g_agg[(size_t)d * 16 + k], ns * h);
            }
        }
    }
}

// ---- pass 6: output projection (fallback path restores g_agg zero invariant) ----
__global__ void k_out(const float* __restrict__ W1, const float* __restrict__ b1,
                      const float* __restrict__ W2, const float* __restrict__ b2,
                      float* __restrict__ out, int n) {
    __shared__ float sc[64];
    __shared__ float sb2[32];
    __shared__ float sW2[512];
    __shared__ float sW1[16], sb1[16];
    int bz = g_b1zero;
    int t = threadIdx.x;
    if (t < 64) sc[t] = g_c[t];
    if (t < 32) sb2[t] = b2[t];
    if (!bz) {
        for (int k = t; k < 512; k += blockDim.x) sW2[k] = W2[k];
        if (t < 16) { sW1[t] = W1[t]; sb1[t] = b1[t]; }
    }
    __syncthreads();
    int v = blockIdx.x * blockDim.x + t;
    if (v >= n) return;

    float o[32];
    float dv = g_dinv[v];
    if (bz) {
        float2 PQ = g_PQ[v];
        float P = dv * PQ.x, Q = dv * PQ.y;
#pragma unroll
        for (int j = 0; j < 32; j++) o[j] = P * sc[j] + Q * sc[32 + j] + sb2[j];
    } else {
        float sv = g_s[v];
        float n2 = dv * dv;
        float tot[16];
        float4* a = reinterpret_cast<float4*>(&g_agg[(size_t)v * 16]);
        float4 z = make_float4(0.f, 0.f, 0.f, 0.f);
#pragma unroll
        for (int q4 = 0; q4 < 4; q4++) {
            float4 av = a[q4];
            a[q4] = z;                 // reset invariant for next replay
            tot[4 * q4 + 0] = av.x; tot[4 * q4 + 1] = av.y;
            tot[4 * q4 + 2] = av.z; tot[4 * q4 + 3] = av.w;
        }
#pragma unroll
        for (int k = 0; k < 16; k++) {
            float h = fmaxf(sv * sW1[k] + sb1[k], 0.f);
            tot[k] = dv * tot[k] + n2 * h;
        }
#pragma unroll
        for (int j = 0; j < 32; j++) {
            float acc = sb2[j];
#pragma unroll
            for (int k = 0; k < 16; k++) acc += tot[k] * sW2[k * 32 + j];
            o[j] = acc;
        }
    }
    float4* po = reinterpret_cast<float4*>(out + (size_t)v * 32);
#pragma unroll
    for (int j = 0; j < 8; j++)
        po[j] = make_float4(o[4 * j], o[4 * j + 1], o[4 * j + 2], o[4 * j + 3]);
}

extern "C" void kernel_launch(void* const* d_in, const int* in_sizes, int n_in,
                              void* d_out, int out_size) {
    const float* x  = (const float*)d_in[0];
    const void*  ei = d_in[1];
    const float* W1 = (const float*)d_in[2];
    const float* b1 = (const float*)d_in[3];
    const float* W2 = (const float*)d_in[4];
    const float* b2 = (const float*)d_in[5];
    float* out = (float*)d_out;

    int N = in_sizes[0];
    int E = in_sizes[1] / 2;

    int gN = (N + BLK - 1) / BLK;

    k_setup<<<1, BLK>>>(ei, W1, b1, W2, E, N);
    k_deg<<<EGRID, BLK>>>(ei, E);
    k_node1<<<gN, BLK>>>(x, N);
    k_scat1<<<EGRID, BLK>>>(ei, E);
    k_node2<<<gN, BLK>>>(N);
    k_scat2<<<EGRID, BLK>>>(ei, W1, b1, E);
    k_out<<<gN, BLK>>>(W1, b1, W2, b2, out, N);
}